// round 1
// baseline (speedup 1.0000x reference)
#include <cuda_runtime.h>

// Problem constants (fixed by setup_inputs)
#define BB 16
#define HH 2048
#define WW 2048
#define SS 5000
#define NST (BB * SS)          // 80000 stations

#define THREADS 256
#define NBLK ((NST + THREADS - 1) / THREADS)   // 313

// Scratch for deterministic two-stage reduction (no device mallocs allowed)
__device__ float g_partials[NBLK];

__global__ __launch_bounds__(THREADS)
void station_loss_kernel(const float* __restrict__ pred,
                         const int*   __restrict__ pos,
                         const float* __restrict__ runoff)
{
    const int tid = blockIdx.x * blockDim.x + threadIdx.x;

    float per_station = 0.0f;
    if (tid < NST) {
        const int b  = tid / SS;
        const int px = pos[2 * tid + 0];   // width index
        const int py = pos[2 * tid + 1];   // height index
        const float* __restrict__ p = pred + (long long)b * (HH * WW);

        // Issue all 9 loads with clamped (always-valid) addresses so ptxas can
        // front-batch them (max MLP); mask invalid taps arithmetically.
        float vals[9];
        float flags[9];
        #pragma unroll
        for (int dy = -1; dy <= 1; dy++) {
            #pragma unroll
            for (int dx = -1; dx <= 1; dx++) {
                const int i = (dy + 1) * 3 + (dx + 1);
                const int y = py + dy;
                const int x = px + dx;
                const bool v = (y >= 0) & (y < HH) & (x >= 0) & (x < WW);
                const int yc = min(max(y, 0), HH - 1);
                const int xc = min(max(x, 0), WW - 1);
                vals[i]  = __ldg(p + yc * WW + xc);
                flags[i] = v ? 1.0f : 0.0f;
            }
        }

        float sum = 0.0f, cnt = 0.0f;
        #pragma unroll
        for (int i = 0; i < 9; i++) {
            sum += vals[i] * flags[i];
            cnt += flags[i];
        }
        const float avg  = sum / cnt;
        const float diff = avg - runoff[tid];
        per_station = diff * diff;
    }

    // Deterministic block reduction: warp shuffle then shared-mem tree.
    __shared__ float smem[THREADS / 32];
    float v = per_station;
    #pragma unroll
    for (int off = 16; off > 0; off >>= 1)
        v += __shfl_down_sync(0xFFFFFFFFu, v, off);
    const int lane = threadIdx.x & 31;
    const int warp = threadIdx.x >> 5;
    if (lane == 0) smem[warp] = v;
    __syncthreads();
    if (warp == 0) {
        v = (lane < THREADS / 32) ? smem[lane] : 0.0f;
        #pragma unroll
        for (int off = 16; off > 0; off >>= 1)
            v += __shfl_down_sync(0xFFFFFFFFu, v, off);
        if (lane == 0) g_partials[blockIdx.x] = v;
    }
}

__global__ __launch_bounds__(512)
void final_reduce_kernel(float* __restrict__ out)
{
    __shared__ float smem[512 / 32];
    float s = 0.0f;
    for (int i = threadIdx.x; i < NBLK; i += 512)
        s += g_partials[i];
    #pragma unroll
    for (int off = 16; off > 0; off >>= 1)
        s += __shfl_down_sync(0xFFFFFFFFu, s, off);
    const int lane = threadIdx.x & 31;
    const int warp = threadIdx.x >> 5;
    if (lane == 0) smem[warp] = s;
    __syncthreads();
    if (warp == 0) {
        s = (lane < 512 / 32) ? smem[lane] : 0.0f;
        #pragma unroll
        for (int off = 16; off > 0; off >>= 1)
            s += __shfl_down_sync(0xFFFFFFFFu, s, off);
        if (lane == 0) out[0] = s / (float)NST;
    }
}

extern "C" void kernel_launch(void* const* d_in, const int* in_sizes, int n_in,
                              void* d_out, int out_size)
{
    const float* pred   = (const float*)d_in[0];  // (16,1,2048,2048) f32
    const int*   pos    = (const int*)  d_in[1];  // (16,5000,2) i32
    const float* runoff = (const float*)d_in[2];  // (16,5000) f32
    float* out = (float*)d_out;

    station_loss_kernel<<<NBLK, THREADS>>>(pred, pos, runoff);
    final_reduce_kernel<<<1, 512>>>(out);
}